// round 9
// baseline (speedup 1.0000x reference)
#include <cuda_runtime.h>
#include <cuda_fp16.h>
#include <math.h>
#include <stdint.h>

// Problem constants
#define Bq 64
#define Aq 256
#define Hq 512
#define Oq 2
#define Tq 32
#define Nq (Bq*Aq)     // 16384 rows
#define G3 (3*Hq)      // 1536
#define MH (Hq/2)      // 256

// ---------------- device globals (no allocation allowed) --------------------
__device__ float g_h0[Nq*Hq];
__device__ float g_h1[Nq*Hq];
__device__ __half g_h0h[Nq*Hq];    // fp16 copy of h0
__device__ __half g_h1h[Nq*Hq];    // fp16 copy of h1
__device__ float g_gate0[Nq*G3];
__device__ float g_gate1[Nq*G3];
__device__ float g_x[Nq*Oq];
__device__ float g_m[Nq*MH];
__device__ __half g_Whh0hi[G3*Hq], g_Whh0lo[G3*Hq];
__device__ __half g_Wih1hi[G3*Hq], g_Wih1lo[G3*Hq];
__device__ __half g_Whh1hi[G3*Hq], g_Whh1lo[G3*Hq];
__device__ __half g_W1hi[MH*Hq],  g_W1lo[MH*Hq];

// ---------------- helpers ----------------------------------------------------
__device__ __forceinline__ uint32_t smem_u32(const void* p) {
    uint32_t a;
    asm("{ .reg .u64 t; cvta.to.shared.u64 t, %1; cvt.u32.u64 %0, t; }" : "=r"(a) : "l"(p));
    return a;
}
__device__ __forceinline__ void cp_async16(uint32_t dst, const void* src) {
    asm volatile("cp.async.cg.shared.global [%0], [%1], 16;" :: "r"(dst), "l"(src) : "memory");
}
__device__ __forceinline__ void ldmatrix_x4(uint32_t& r0, uint32_t& r1, uint32_t& r2, uint32_t& r3, uint32_t addr) {
    asm volatile("ldmatrix.sync.aligned.m8n8.x4.shared.b16 {%0,%1,%2,%3}, [%4];"
                 : "=r"(r0), "=r"(r1), "=r"(r2), "=r"(r3) : "r"(addr));
}
__device__ __forceinline__ void mma16816(float* d, uint32_t a0, uint32_t a1, uint32_t a2, uint32_t a3,
                                         uint32_t b0, uint32_t b1) {
    asm volatile("mma.sync.aligned.m16n8k16.row.col.f32.f16.f16.f32 "
                 "{%0,%1,%2,%3}, {%4,%5,%6,%7}, {%8,%9}, {%0,%1,%2,%3};"
                 : "+f"(d[0]), "+f"(d[1]), "+f"(d[2]), "+f"(d[3])
                 : "r"(a0), "r"(a1), "r"(a2), "r"(a3), "r"(b0), "r"(b1));
}

// ---------------- GEMM (mma.sync fp16, 2-pass hi/lo weight split) ------------
// C[Nq x M] = A[Nq x 512] @ (Whi + Wlo)[M x 512]^T   with A = fp16(act)
// CTA tile 128x128, 128 threads = 4 warps (2x2), warp tile 64x64.
// K chunks of 64 halves, 3-stage cp.async pipeline, 2 CTAs/SM.
// Rationale: 64x64 warps cut cross-warp smem re-reads (A x2, W x2 instead of
// W x4), pushing smem below the tensor-pipe floor.
// Dual-problem via blockIdx.z (wave-tail packing of independent GEMMs).
#define BM 128
#define BN 128
#define BKH 64                      // halves per chunk
#define ROWB 144                    // smem row stride bytes (72 halves, padded)
#define STAGE_BYTES ((BM + BN) * ROWB)   // 36864
#define NSTAGE 3
#define GEMM_SMEM (NSTAGE * STAGE_BYTES) // 110592
#define NSEG 2
#define NCH (NSEG * 8)              // 16 chunks
#define GTH 128                     // gemm threads

struct GemmSegs {
    const __half* a[NSEG];
    const __half* w[NSEG];
};

__global__ __launch_bounds__(GTH, 2) void gemm_mma(
    GemmSegs segsA, GemmSegs segsB, float* __restrict__ CA, float* __restrict__ CB,
    int M, const float* __restrict__ bias, int relu)
{
    extern __shared__ char sm[];
    const int tid  = threadIdx.x;
    const int warp = tid >> 5;
    const int lane = tid & 31;
    const int rowBase = blockIdx.y * BM;
    const int colBase = blockIdx.x * BN;
    const int wr = (warp & 1) * 64;      // warp row offset (0/64)
    const int wc = (warp >> 1) * 64;     // warp col offset (0/64)

    const GemmSegs& segs = blockIdx.z ? segsB : segsA;
    float* __restrict__ C = blockIdx.z ? CB : CA;

    const uint32_t sbase = smem_u32(sm);

    float acc[4][8][4];
#pragma unroll
    for (int i = 0; i < 4; i++)
#pragma unroll
        for (int j = 0; j < 8; j++)
#pragma unroll
            for (int v = 0; v < 4; v++) acc[i][j][v] = 0.0f;

    // ---- chunk loader: 128 threads, 8 iters each for A and W ---------------
#define LOAD_CHUNK(c, s) do { \
        int _seg  = (c) >> 3; \
        int _koff = ((c) & 7) * BKH; \
        const __half* _Ag = segs.a[_seg] + (size_t)rowBase * Hq + _koff; \
        const __half* _Wg = segs.w[_seg] + (size_t)colBase * Hq + _koff; \
        uint32_t _ab = sbase + (s) * STAGE_BYTES; \
        uint32_t _wb = _ab + BM * ROWB; \
        _Pragma("unroll") \
        for (int _i = 0; _i < 8; _i++) { \
            int _lin = tid + _i * GTH; \
            int _r = _lin >> 3, _sg = _lin & 7; \
            cp_async16(_ab + _r * ROWB + _sg * 16, _Ag + (size_t)_r * Hq + _sg * 8); \
            cp_async16(_wb + _r * ROWB + _sg * 16, _Wg + (size_t)_r * Hq + _sg * 8); \
        } \
        asm volatile("cp.async.commit_group;" ::: "memory"); \
    } while (0)

    LOAD_CHUNK(0, 0);
    LOAD_CHUNK(1, 1);

    // ldmatrix base addresses (stage offset added in loop)
    // A x4: lanes 0-15 -> rows wr+0..15 @k-bytes 0; lanes 16-31 -> same rows @k-bytes 16
    const uint32_t aAddrBase = (wr + (lane & 15)) * ROWB + (lane >> 4) * 16;
    // W x4: lanes 0-7 -> n-rows wc+0..7 @k0; 8-15 -> same @k8; 16-23 -> wc+8..15 @k0; 24-31 @k8
    const uint32_t wAddrBase = BM * ROWB
        + (wc + (lane & 7) + ((lane >> 4) & 1) * 8) * ROWB
        + ((lane >> 3) & 1) * 16;

    for (int c = 0; c < NCH; c++) {
        if (c + 2 < NCH) {
            LOAD_CHUNK(c + 2, (c + 2) % NSTAGE);
            asm volatile("cp.async.wait_group 2;" ::: "memory");
        } else if (c + 1 < NCH) {
            asm volatile("cp.async.wait_group 1;" ::: "memory");
        } else {
            asm volatile("cp.async.wait_group 0;" ::: "memory");
        }
        __syncthreads();

        const uint32_t stageOff = sbase + (c % NSTAGE) * STAGE_BYTES;
#pragma unroll
        for (int ks = 0; ks < 4; ks++) {
            uint32_t af[4][4], bf[4][4];
#pragma unroll
            for (int rt = 0; rt < 4; rt++)
                ldmatrix_x4(af[rt][0], af[rt][1], af[rt][2], af[rt][3],
                            stageOff + aAddrBase + rt * 16 * ROWB + ks * 32);
#pragma unroll
            for (int cp = 0; cp < 4; cp++)
                ldmatrix_x4(bf[cp][0], bf[cp][1], bf[cp][2], bf[cp][3],
                            stageOff + wAddrBase + cp * 16 * ROWB + ks * 32);
#pragma unroll
            for (int rt = 0; rt < 4; rt++)
#pragma unroll
                for (int ct = 0; ct < 8; ct++) {
                    int cp = ct >> 1, hf = (ct & 1) * 2;
                    mma16816(acc[rt][ct], af[rt][0], af[rt][1], af[rt][2], af[rt][3],
                             bf[cp][hf], bf[cp][hf + 1]);
                }
        }
        __syncthreads();
    }

    // ---- epilogue ----
    const int gid = lane >> 2;
    const int tig = lane & 3;
#pragma unroll
    for (int rt = 0; rt < 4; rt++) {
        int row0 = rowBase + wr + rt * 16 + gid;
#pragma unroll
        for (int ct = 0; ct < 8; ct++) {
            int col = colBase + wc + ct * 8 + tig * 2;
            float2 v0 = make_float2(acc[rt][ct][0], acc[rt][ct][1]);
            float2 v1 = make_float2(acc[rt][ct][2], acc[rt][ct][3]);
            if (bias) {
                float b0 = bias[col], b1 = bias[col + 1];
                v0.x += b0; v0.y += b1; v1.x += b0; v1.y += b1;
            }
            if (relu) {
                v0.x = fmaxf(v0.x, 0.f); v0.y = fmaxf(v0.y, 0.f);
                v1.x = fmaxf(v1.x, 0.f); v1.y = fmaxf(v1.y, 0.f);
            }
            *reinterpret_cast<float2*>(C + (size_t)row0 * M + col) = v0;
            *reinterpret_cast<float2*>(C + (size_t)(row0 + 8) * M + col) = v1;
        }
    }
#undef LOAD_CHUNK
}

// ---------------- fused weight split (fp16 hi/lo, all 4 weights) -------------
#define WSZ (G3*Hq)          // 786432
#define SPLIT_TOTAL (3*WSZ + MH*Hq)
__global__ void split_all(const float* __restrict__ Whh0, const float* __restrict__ Wih1,
                          const float* __restrict__ Whh1, const float* __restrict__ W1)
{
    int idx = blockIdx.x * blockDim.x + threadIdx.x;
    if (idx >= SPLIT_TOTAL) return;
    const float* src; __half* hi; __half* lo; int i;
    if (idx < WSZ)            { src = Whh0; hi = g_Whh0hi; lo = g_Whh0lo; i = idx; }
    else if (idx < 2*WSZ)     { src = Wih1; hi = g_Wih1hi; lo = g_Wih1lo; i = idx - WSZ; }
    else if (idx < 3*WSZ)     { src = Whh1; hi = g_Whh1hi; lo = g_Whh1lo; i = idx - 2*WSZ; }
    else                      { src = W1;   hi = g_W1hi;   lo = g_W1lo;   i = idx - 3*WSZ; }
    float v = src[i];
    __half h = __float2half_rn(v);
    hi[i] = h;
    lo[i] = __float2half_rn(v - __half2float(h));
}

// ---------------- init -------------------------------------------------------
// hidden row i = a*B + b holds social[b][a]
__global__ void init_kernel(const float* __restrict__ social,
                            const float* __restrict__ lastpos)
{
    int idx = blockIdx.x * blockDim.x + threadIdx.x;
    if (idx < Nq * Hq) {
        int i = idx >> 9;
        int cch = idx & (Hq - 1);
        int b = i & (Bq - 1);
        int a = i >> 6;
        float v = social[(b * Aq + a) * Hq + cch];
        g_h0[idx] = v;
        g_h1[idx] = v;
        __half h = __float2half_rn(v);
        g_h0h[idx] = h;
        g_h1h[idx] = h;
    }
    if (idx < Nq * Oq) g_x[idx] = lastpos[idx];
}

// ---------------- GRU combine layer 0 (vectorized x4, inline x@Wih0) ---------
__global__ void combine0(const float* __restrict__ gh,
                         float* __restrict__ h,
                         __half* __restrict__ hh,
                         const float* __restrict__ Wih0,
                         const float* __restrict__ bih,
                         const float* __restrict__ bhh)
{
    int v4 = blockIdx.x * blockDim.x + threadIdx.x;   // Nq*Hq/4 threads
    if (v4 >= Nq * Hq / 4) return;
    int idx = v4 * 4;
    int i = idx >> 9;
    int j = idx & (Hq - 1);

    float x0 = g_x[i * 2 + 0];
    float x1 = g_x[i * 2 + 1];

    const float* g = gh + (size_t)i * G3;
    float4 gr = *(const float4*)(g + 0 * Hq + j);
    float4 gz = *(const float4*)(g + 1 * Hq + j);
    float4 gn = *(const float4*)(g + 2 * Hq + j);
    float4 br_i = *(const float4*)(bih + 0 * Hq + j);
    float4 bz_i = *(const float4*)(bih + 1 * Hq + j);
    float4 bn_i = *(const float4*)(bih + 2 * Hq + j);
    float4 br_h = *(const float4*)(bhh + 0 * Hq + j);
    float4 bz_h = *(const float4*)(bhh + 1 * Hq + j);
    float4 bn_h = *(const float4*)(bhh + 2 * Hq + j);
    float4 hp = *(const float4*)(h + idx);

    float4 wr0 = *(const float4*)(Wih0 + (0 * Hq + j) * 2);
    float4 wr1 = *(const float4*)(Wih0 + (0 * Hq + j) * 2 + 4);
    float4 wz0 = *(const float4*)(Wih0 + (1 * Hq + j) * 2);
    float4 wz1 = *(const float4*)(Wih0 + (1 * Hq + j) * 2 + 4);
    float4 wn0 = *(const float4*)(Wih0 + (2 * Hq + j) * 2);
    float4 wn1 = *(const float4*)(Wih0 + (2 * Hq + j) * 2 + 4);

    float ho[4]; __half hhv[4];
#pragma unroll
    for (int u = 0; u < 4; u++) {
        float wir0 = (u < 2) ? ((u == 0) ? wr0.x : wr0.z) : ((u == 2) ? wr1.x : wr1.z);
        float wir1 = (u < 2) ? ((u == 0) ? wr0.y : wr0.w) : ((u == 2) ? wr1.y : wr1.w);
        float wiz0 = (u < 2) ? ((u == 0) ? wz0.x : wz0.z) : ((u == 2) ? wz1.x : wz1.z);
        float wiz1 = (u < 2) ? ((u == 0) ? wz0.y : wz0.w) : ((u == 2) ? wz1.y : wz1.w);
        float win0 = (u < 2) ? ((u == 0) ? wn0.x : wn0.z) : ((u == 2) ? wn1.x : wn1.z);
        float win1 = (u < 2) ? ((u == 0) ? wn0.y : wn0.w) : ((u == 2) ? wn1.y : wn1.w);

        float grv = (&gr.x)[u], gzv = (&gz.x)[u], gnv = (&gn.x)[u];
        float ir  = x0 * wir0 + x1 * wir1 + (&br_i.x)[u];
        float iz  = x0 * wiz0 + x1 * wiz1 + (&bz_i.x)[u];
        float in_ = x0 * win0 + x1 * win1 + (&bn_i.x)[u];
        float hr = grv + (&br_h.x)[u];
        float hz = gzv + (&bz_h.x)[u];
        float hn = gnv + (&bn_h.x)[u];

        float r = 1.0f / (1.0f + expf(-(ir + hr)));
        float z = 1.0f / (1.0f + expf(-(iz + hz)));
        float n = tanhf(in_ + r * hn);
        float v = (1.0f - z) * n + z * (&hp.x)[u];
        ho[u] = v;
        hhv[u] = __float2half_rn(v);
    }
    *(float4*)(h + idx) = make_float4(ho[0], ho[1], ho[2], ho[3]);
    *(uint2*)(hh + idx) = *(uint2*)hhv;
}

// ---------------- GRU combine layer 1 (vectorized x4) ------------------------
__global__ void combine1(const float* __restrict__ gi,
                         const float* __restrict__ gh,
                         float* __restrict__ h,
                         __half* __restrict__ hh,
                         const float* __restrict__ bih,
                         const float* __restrict__ bhh)
{
    int v4 = blockIdx.x * blockDim.x + threadIdx.x;
    if (v4 >= Nq * Hq / 4) return;
    int idx = v4 * 4;
    int i = idx >> 9;
    int j = idx & (Hq - 1);

    const float* a = gi + (size_t)i * G3;
    const float* g = gh + (size_t)i * G3;

    float4 ar = *(const float4*)(a + 0 * Hq + j);
    float4 az = *(const float4*)(a + 1 * Hq + j);
    float4 an = *(const float4*)(a + 2 * Hq + j);
    float4 gr = *(const float4*)(g + 0 * Hq + j);
    float4 gz = *(const float4*)(g + 1 * Hq + j);
    float4 gn = *(const float4*)(g + 2 * Hq + j);
    float4 br_i = *(const float4*)(bih + 0 * Hq + j);
    float4 bz_i = *(const float4*)(bih + 1 * Hq + j);
    float4 bn_i = *(const float4*)(bih + 2 * Hq + j);
    float4 br_h = *(const float4*)(bhh + 0 * Hq + j);
    float4 bz_h = *(const float4*)(bhh + 1 * Hq + j);
    float4 bn_h = *(const float4*)(bhh + 2 * Hq + j);
    float4 hp = *(const float4*)(h + idx);

    float ho[4]; __half hhv[4];
#pragma unroll
    for (int u = 0; u < 4; u++) {
        float ir  = (&ar.x)[u] + (&br_i.x)[u];
        float iz  = (&az.x)[u] + (&bz_i.x)[u];
        float in_ = (&an.x)[u] + (&bn_i.x)[u];
        float hr  = (&gr.x)[u] + (&br_h.x)[u];
        float hz  = (&gz.x)[u] + (&bz_h.x)[u];
        float hn  = (&gn.x)[u] + (&bn_h.x)[u];

        float r = 1.0f / (1.0f + expf(-(ir + hr)));
        float z = 1.0f / (1.0f + expf(-(iz + hz)));
        float n = tanhf(in_ + r * hn);
        float v = (1.0f - z) * n + z * (&hp.x)[u];
        ho[u] = v;
        hhv[u] = __float2half_rn(v);
    }
    *(float4*)(h + idx) = make_float4(ho[0], ho[1], ho[2], ho[3]);
    *(uint2*)(hh + idx) = *(uint2*)hhv;
}

// ---------------- prediction: pred = Mh @ W2^T + b2 --------------------------
__global__ void pred_kernel(const float* __restrict__ Mh,
                            const float* __restrict__ W2,
                            const float* __restrict__ b2,
                            float* __restrict__ out, int t)
{
    int gwarp = (blockIdx.x * blockDim.x + threadIdx.x) >> 5;
    int lane  = threadIdx.x & 31;
    if (gwarp >= Nq) return;

    const float* mrow = Mh + (size_t)gwarp * MH;
    float s0 = 0.0f, s1 = 0.0f;
#pragma unroll
    for (int u = 0; u < 8; u++) {
        float m = mrow[lane + 32 * u];
        s0 = fmaf(m, W2[      lane + 32 * u], s0);
        s1 = fmaf(m, W2[MH +  lane + 32 * u], s1);
    }
#pragma unroll
    for (int off = 16; off; off >>= 1) {
        s0 += __shfl_xor_sync(0xFFFFFFFFu, s0, off);
        s1 += __shfl_xor_sync(0xFFFFFFFFu, s1, off);
    }
    if (lane == 0) {
        s0 += b2[0];
        s1 += b2[1];
        g_x[gwarp * 2 + 0] = s0;
        g_x[gwarp * 2 + 1] = s1;
        int b = gwarp >> 8;
        int a = gwarp & (Aq - 1);
        float* o = out + (((size_t)b * Tq + t) * Aq + a) * Oq;
        o[0] = s0;
        o[1] = s1;
    }
}

// ---------------- launch -----------------------------------------------------
extern "C" void kernel_launch(void* const* d_in, const int* in_sizes, int n_in,
                              void* d_out, int out_size)
{
    const float* social  = (const float*)d_in[0];
    const float* lastpos = (const float*)d_in[1];
    const float* Wih0    = (const float*)d_in[2];
    const float* Whh0    = (const float*)d_in[3];
    const float* bih0    = (const float*)d_in[4];
    const float* bhh0    = (const float*)d_in[5];
    const float* Wih1    = (const float*)d_in[6];
    const float* Whh1    = (const float*)d_in[7];
    const float* bih1    = (const float*)d_in[8];
    const float* bhh1    = (const float*)d_in[9];
    const float* W1      = (const float*)d_in[10];
    const float* b1      = (const float*)d_in[11];
    const float* W2      = (const float*)d_in[12];
    const float* b2      = (const float*)d_in[13];
    float* out = (float*)d_out;

    float *h0, *h1, *gate0, *gate1, *mbuf;
    __half *h0h, *h1h;
    __half *whh0hi, *whh0lo, *wih1hi, *wih1lo, *whh1hi, *whh1lo, *w1hi, *w1lo;
    cudaGetSymbolAddress((void**)&h0,    g_h0);
    cudaGetSymbolAddress((void**)&h1,    g_h1);
    cudaGetSymbolAddress((void**)&gate0, g_gate0);
    cudaGetSymbolAddress((void**)&gate1, g_gate1);
    cudaGetSymbolAddress((void**)&mbuf,  g_m);
    cudaGetSymbolAddress((void**)&h0h,   g_h0h);
    cudaGetSymbolAddress((void**)&h1h,   g_h1h);
    cudaGetSymbolAddress((void**)&whh0hi, g_Whh0hi);
    cudaGetSymbolAddress((void**)&whh0lo, g_Whh0lo);
    cudaGetSymbolAddress((void**)&wih1hi, g_Wih1hi);
    cudaGetSymbolAddress((void**)&wih1lo, g_Wih1lo);
    cudaGetSymbolAddress((void**)&whh1hi, g_Whh1hi);
    cudaGetSymbolAddress((void**)&whh1lo, g_Whh1lo);
    cudaGetSymbolAddress((void**)&w1hi,  g_W1hi);
    cudaGetSymbolAddress((void**)&w1lo,  g_W1lo);

    cudaFuncSetAttribute(gemm_mma, cudaFuncAttributeMaxDynamicSharedMemorySize, GEMM_SMEM);

    // split weights (fused, idempotent, every call)
    split_all<<<(SPLIT_TOTAL + 255) / 256, 256>>>(Whh0, Wih1, Whh1, W1);

    init_kernel<<<(Nq * Hq + 255) / 256, 256>>>(social, lastpos);

    dim3 gridGateDual(G3 / BN, Nq / BM, 2);  // 12 x 128 x 2
    dim3 gridGate(G3 / BN, Nq / BM, 1);      // 12 x 128
    dim3 gridMlp(MH / BN, Nq / BM, 1);       // 2  x 128
    int combBlocks = (Nq * Hq / 4 + 255) / 256;

    for (int t = 0; t < Tq; t++) {
        // merged: Gh0 = h0 @ Whh0^T  and  Gh1 = h1 @ Whh1^T  (independent)
        GemmSegs s0; s0.a[0] = h0h; s0.a[1] = h0h;
                     s0.w[0] = whh0hi; s0.w[1] = whh0lo;
        GemmSegs s2; s2.a[0] = h1h; s2.a[1] = h1h;
                     s2.w[0] = whh1hi; s2.w[1] = whh1lo;
        gemm_mma<<<gridGateDual, GTH, GEMM_SMEM>>>(s0, s2, gate0, gate1, G3, nullptr, 0);
        combine0<<<combBlocks, 256>>>(gate0, h0, h0h, Wih0, bih0, bhh0);

        // Gi1 = h0n @ Wih1^T
        GemmSegs s1; s1.a[0] = h0h; s1.a[1] = h0h;
                     s1.w[0] = wih1hi; s1.w[1] = wih1lo;
        gemm_mma<<<gridGate, GTH, GEMM_SMEM>>>(s1, s1, gate0, gate0, G3, nullptr, 0);
        combine1<<<combBlocks, 256>>>(gate0, gate1, h1, h1h, bih1, bhh1);

        // MLP hidden: m = relu(h1 @ W1^T + b1)
        GemmSegs s3; s3.a[0] = h1h; s3.a[1] = h1h;
                     s3.w[0] = w1hi; s3.w[1] = w1lo;
        gemm_mma<<<gridMlp, GTH, GEMM_SMEM>>>(s3, s3, mbuf, mbuf, MH, b1, 1);
        pred_kernel<<<Nq * 32 / 256, 256>>>(mbuf, W2, b2, out, t);
    }
}

// round 10
// speedup vs baseline: 1.0378x; 1.0378x over previous
#include <cuda_runtime.h>
#include <cuda_fp16.h>
#include <math.h>
#include <stdint.h>

// Problem constants
#define Bq 64
#define Aq 256
#define Hq 512
#define Oq 2
#define Tq 32
#define Nq (Bq*Aq)     // 16384 rows
#define G3 (3*Hq)      // 1536
#define MH (Hq/2)      // 256

// ---------------- device globals (no allocation allowed) --------------------
__device__ float g_h0[Nq*Hq];
__device__ float g_h1[Nq*Hq];
__device__ __half g_h0h[Nq*Hq];    // fp16 copy of h0
__device__ __half g_h1h[Nq*Hq];    // fp16 copy of h1
__device__ float g_gate0[Nq*G3];
__device__ float g_gate1[Nq*G3];
__device__ float g_x[Nq*Oq];
__device__ float g_m[Nq*MH];
__device__ __half g_Whh0hi[G3*Hq], g_Whh0lo[G3*Hq];
__device__ __half g_Wih1hi[G3*Hq], g_Wih1lo[G3*Hq];
__device__ __half g_Whh1hi[G3*Hq], g_Whh1lo[G3*Hq];
__device__ __half g_W1hi[MH*Hq],  g_W1lo[MH*Hq];

// ---------------- helpers ----------------------------------------------------
__device__ __forceinline__ uint32_t smem_u32(const void* p) {
    uint32_t a;
    asm("{ .reg .u64 t; cvta.to.shared.u64 t, %1; cvt.u32.u64 %0, t; }" : "=r"(a) : "l"(p));
    return a;
}
__device__ __forceinline__ void cp_async16(uint32_t dst, const void* src) {
    asm volatile("cp.async.cg.shared.global [%0], [%1], 16;" :: "r"(dst), "l"(src) : "memory");
}
__device__ __forceinline__ void ldmatrix_x4(uint32_t& r0, uint32_t& r1, uint32_t& r2, uint32_t& r3, uint32_t addr) {
    asm volatile("ldmatrix.sync.aligned.m8n8.x4.shared.b16 {%0,%1,%2,%3}, [%4];"
                 : "=r"(r0), "=r"(r1), "=r"(r2), "=r"(r3) : "r"(addr));
}
__device__ __forceinline__ void mma16816(float* d, uint32_t a0, uint32_t a1, uint32_t a2, uint32_t a3,
                                         uint32_t b0, uint32_t b1) {
    asm volatile("mma.sync.aligned.m16n8k16.row.col.f32.f16.f16.f32 "
                 "{%0,%1,%2,%3}, {%4,%5,%6,%7}, {%8,%9}, {%0,%1,%2,%3};"
                 : "+f"(d[0]), "+f"(d[1]), "+f"(d[2]), "+f"(d[3])
                 : "r"(a0), "r"(a1), "r"(a2), "r"(a3), "r"(b0), "r"(b1));
}

// ---------------- GEMM (mma.sync fp16, 2-pass hi/lo weight split) ------------
// C[Nq x M] = A[Nq x 512] @ (Whi + Wlo)[M x 512]^T   with A = fp16(act)
// R8 config: tile 128x128, 8 warps as 4 row-groups x 2 col-groups (32x64 warp
// tile), K chunks of 64 halves, 3-stage cp.async pipeline, 2 CTAs/SM.
// NEW: single __syncthreads per chunk. Order: wait(chunk c) -> sync -> issue
// load c+2 -> MMA c. Load c+2 overwrites stage (c-1)%3, whose readers all
// passed the sync. wait_group 1 before issuing keeps <=1 pending group.
// Dual-problem via blockIdx.z (wave-tail packing of independent GEMMs).
#define BM 128
#define BN 128
#define BKH 64                      // halves per chunk
#define ROWB 144                    // smem row stride bytes (72 halves, padded)
#define STAGE_BYTES ((BM + BN) * ROWB)   // 36864
#define NSTAGE 3
#define GEMM_SMEM (NSTAGE * STAGE_BYTES) // 110592
#define NSEG 2
#define NCH (NSEG * 8)              // 16 chunks

struct GemmSegs {
    const __half* a[NSEG];
    const __half* w[NSEG];
};

__global__ __launch_bounds__(256, 2) void gemm_mma(
    GemmSegs segsA, GemmSegs segsB, float* __restrict__ CA, float* __restrict__ CB,
    int M, const float* __restrict__ bias, int relu)
{
    extern __shared__ char sm[];
    const int tid  = threadIdx.x;
    const int warp = tid >> 5;
    const int lane = tid & 31;
    const int rowBase = blockIdx.y * BM;
    const int colBase = blockIdx.x * BN;
    const int wr = (warp & 3) * 32;      // warp row offset (0/32/64/96)
    const int wc = (warp >> 2) * 64;     // warp col offset (0/64)

    const GemmSegs& segs = blockIdx.z ? segsB : segsA;
    float* __restrict__ C = blockIdx.z ? CB : CA;

    const uint32_t sbase = smem_u32(sm);

    float acc[2][8][4];
#pragma unroll
    for (int i = 0; i < 2; i++)
#pragma unroll
        for (int j = 0; j < 8; j++)
#pragma unroll
            for (int v = 0; v < 4; v++) acc[i][j][v] = 0.0f;

    // ---- chunk loader: each thread copies 4 A row-segments + 4 W -----------
#define LOAD_CHUNK(c, s) do { \
        int _seg  = (c) >> 3; \
        int _koff = ((c) & 7) * BKH; \
        const __half* _Ag = segs.a[_seg] + (size_t)rowBase * Hq + _koff; \
        const __half* _Wg = segs.w[_seg] + (size_t)colBase * Hq + _koff; \
        uint32_t _ab = sbase + (s) * STAGE_BYTES; \
        uint32_t _wb = _ab + BM * ROWB; \
        _Pragma("unroll") \
        for (int _i = 0; _i < 4; _i++) { \
            int _lin = tid + _i * 256; \
            int _r = _lin >> 3, _sg = _lin & 7; \
            cp_async16(_ab + _r * ROWB + _sg * 16, _Ag + (size_t)_r * Hq + _sg * 8); \
            cp_async16(_wb + _r * ROWB + _sg * 16, _Wg + (size_t)_r * Hq + _sg * 8); \
        } \
        asm volatile("cp.async.commit_group;" ::: "memory"); \
    } while (0)

    LOAD_CHUNK(0, 0);
    LOAD_CHUNK(1, 1);

    // ldmatrix base addresses (stage offset added in loop)
    // A x4: lanes 0-15 -> rows wr+0..15 @k-bytes 0; lanes 16-31 -> same rows @k-bytes 16
    const uint32_t aAddrBase = (wr + (lane & 15)) * ROWB + (lane >> 4) * 16;
    // B x4: lanes 0-7 -> n-rows wc+0..7 @k0; 8-15 -> same @k8; 16-23 -> wc+8..15 @k0; 24-31 @k8
    const uint32_t wAddrBase = BM * ROWB
        + (wc + (lane & 7) + ((lane >> 4) & 1) * 8) * ROWB
        + ((lane >> 3) & 1) * 16;

    for (int c = 0; c < NCH; c++) {
        // wait for chunk c (issued groups beyond c: at most c+1 -> 1 pending)
        if (c + 1 < NCH) {
            asm volatile("cp.async.wait_group 1;" ::: "memory");
        } else {
            asm volatile("cp.async.wait_group 0;" ::: "memory");
        }
        __syncthreads();   // all warps done with chunk c-1 MMAs; stage (c+2)%3 free

        if (c + 2 < NCH) LOAD_CHUNK(c + 2, (c + 2) % NSTAGE);

        const uint32_t stageOff = sbase + (c % NSTAGE) * STAGE_BYTES;
#pragma unroll
        for (int ks = 0; ks < 4; ks++) {
            uint32_t af[2][4], bf[4][4];
#pragma unroll
            for (int rt = 0; rt < 2; rt++)
                ldmatrix_x4(af[rt][0], af[rt][1], af[rt][2], af[rt][3],
                            stageOff + aAddrBase + rt * 16 * ROWB + ks * 32);
#pragma unroll
            for (int cp = 0; cp < 4; cp++)
                ldmatrix_x4(bf[cp][0], bf[cp][1], bf[cp][2], bf[cp][3],
                            stageOff + wAddrBase + cp * 16 * ROWB + ks * 32);
#pragma unroll
            for (int rt = 0; rt < 2; rt++)
#pragma unroll
                for (int ct = 0; ct < 8; ct++) {
                    int cp = ct >> 1, hf = (ct & 1) * 2;
                    mma16816(acc[rt][ct], af[rt][0], af[rt][1], af[rt][2], af[rt][3],
                             bf[cp][hf], bf[cp][hf + 1]);
                }
        }
    }

    // ---- epilogue ----
    const int gid = lane >> 2;
    const int tig = lane & 3;
#pragma unroll
    for (int rt = 0; rt < 2; rt++) {
        int row0 = rowBase + wr + rt * 16 + gid;
#pragma unroll
        for (int ct = 0; ct < 8; ct++) {
            int col = colBase + wc + ct * 8 + tig * 2;
            float2 v0 = make_float2(acc[rt][ct][0], acc[rt][ct][1]);
            float2 v1 = make_float2(acc[rt][ct][2], acc[rt][ct][3]);
            if (bias) {
                float b0 = bias[col], b1 = bias[col + 1];
                v0.x += b0; v0.y += b1; v1.x += b0; v1.y += b1;
            }
            if (relu) {
                v0.x = fmaxf(v0.x, 0.f); v0.y = fmaxf(v0.y, 0.f);
                v1.x = fmaxf(v1.x, 0.f); v1.y = fmaxf(v1.y, 0.f);
            }
            *reinterpret_cast<float2*>(C + (size_t)row0 * M + col) = v0;
            *reinterpret_cast<float2*>(C + (size_t)(row0 + 8) * M + col) = v1;
        }
    }
#undef LOAD_CHUNK
}

// ---------------- fused weight split (fp16 hi/lo, all 4 weights) -------------
#define WSZ (G3*Hq)          // 786432
#define SPLIT_TOTAL (3*WSZ + MH*Hq)
__global__ void split_all(const float* __restrict__ Whh0, const float* __restrict__ Wih1,
                          const float* __restrict__ Whh1, const float* __restrict__ W1)
{
    int idx = blockIdx.x * blockDim.x + threadIdx.x;
    if (idx >= SPLIT_TOTAL) return;
    const float* src; __half* hi; __half* lo; int i;
    if (idx < WSZ)            { src = Whh0; hi = g_Whh0hi; lo = g_Whh0lo; i = idx; }
    else if (idx < 2*WSZ)     { src = Wih1; hi = g_Wih1hi; lo = g_Wih1lo; i = idx - WSZ; }
    else if (idx < 3*WSZ)     { src = Whh1; hi = g_Whh1hi; lo = g_Whh1lo; i = idx - 2*WSZ; }
    else                      { src = W1;   hi = g_W1hi;   lo = g_W1lo;   i = idx - 3*WSZ; }
    float v = src[i];
    __half h = __float2half_rn(v);
    hi[i] = h;
    lo[i] = __float2half_rn(v - __half2float(h));
}

// ---------------- init -------------------------------------------------------
// hidden row i = a*B + b holds social[b][a]
__global__ void init_kernel(const float* __restrict__ social,
                            const float* __restrict__ lastpos)
{
    int idx = blockIdx.x * blockDim.x + threadIdx.x;
    if (idx < Nq * Hq) {
        int i = idx >> 9;
        int cch = idx & (Hq - 1);
        int b = i & (Bq - 1);
        int a = i >> 6;
        float v = social[(b * Aq + a) * Hq + cch];
        g_h0[idx] = v;
        g_h1[idx] = v;
        __half h = __float2half_rn(v);
        g_h0h[idx] = h;
        g_h1h[idx] = h;
    }
    if (idx < Nq * Oq) g_x[idx] = lastpos[idx];
}

// ---------------- GRU combine layer 0 (vectorized x4, inline x@Wih0) ---------
__global__ void combine0(const float* __restrict__ gh,
                         float* __restrict__ h,
                         __half* __restrict__ hh,
                         const float* __restrict__ Wih0,
                         const float* __restrict__ bih,
                         const float* __restrict__ bhh)
{
    int v4 = blockIdx.x * blockDim.x + threadIdx.x;   // Nq*Hq/4 threads
    if (v4 >= Nq * Hq / 4) return;
    int idx = v4 * 4;
    int i = idx >> 9;
    int j = idx & (Hq - 1);

    float x0 = g_x[i * 2 + 0];
    float x1 = g_x[i * 2 + 1];

    const float* g = gh + (size_t)i * G3;
    float4 gr = *(const float4*)(g + 0 * Hq + j);
    float4 gz = *(const float4*)(g + 1 * Hq + j);
    float4 gn = *(const float4*)(g + 2 * Hq + j);
    float4 br_i = *(const float4*)(bih + 0 * Hq + j);
    float4 bz_i = *(const float4*)(bih + 1 * Hq + j);
    float4 bn_i = *(const float4*)(bih + 2 * Hq + j);
    float4 br_h = *(const float4*)(bhh + 0 * Hq + j);
    float4 bz_h = *(const float4*)(bhh + 1 * Hq + j);
    float4 bn_h = *(const float4*)(bhh + 2 * Hq + j);
    float4 hp = *(const float4*)(h + idx);

    float4 wr0 = *(const float4*)(Wih0 + (0 * Hq + j) * 2);
    float4 wr1 = *(const float4*)(Wih0 + (0 * Hq + j) * 2 + 4);
    float4 wz0 = *(const float4*)(Wih0 + (1 * Hq + j) * 2);
    float4 wz1 = *(const float4*)(Wih0 + (1 * Hq + j) * 2 + 4);
    float4 wn0 = *(const float4*)(Wih0 + (2 * Hq + j) * 2);
    float4 wn1 = *(const float4*)(Wih0 + (2 * Hq + j) * 2 + 4);

    float ho[4]; __half hhv[4];
#pragma unroll
    for (int u = 0; u < 4; u++) {
        float wir0 = (u < 2) ? ((u == 0) ? wr0.x : wr0.z) : ((u == 2) ? wr1.x : wr1.z);
        float wir1 = (u < 2) ? ((u == 0) ? wr0.y : wr0.w) : ((u == 2) ? wr1.y : wr1.w);
        float wiz0 = (u < 2) ? ((u == 0) ? wz0.x : wz0.z) : ((u == 2) ? wz1.x : wz1.z);
        float wiz1 = (u < 2) ? ((u == 0) ? wz0.y : wz0.w) : ((u == 2) ? wz1.y : wz1.w);
        float win0 = (u < 2) ? ((u == 0) ? wn0.x : wn0.z) : ((u == 2) ? wn1.x : wn1.z);
        float win1 = (u < 2) ? ((u == 0) ? wn0.y : wn0.w) : ((u == 2) ? wn1.y : wn1.w);

        float grv = (&gr.x)[u], gzv = (&gz.x)[u], gnv = (&gn.x)[u];
        float ir  = x0 * wir0 + x1 * wir1 + (&br_i.x)[u];
        float iz  = x0 * wiz0 + x1 * wiz1 + (&bz_i.x)[u];
        float in_ = x0 * win0 + x1 * win1 + (&bn_i.x)[u];
        float hr = grv + (&br_h.x)[u];
        float hz = gzv + (&bz_h.x)[u];
        float hn = gnv + (&bn_h.x)[u];

        float r = 1.0f / (1.0f + expf(-(ir + hr)));
        float z = 1.0f / (1.0f + expf(-(iz + hz)));
        float n = tanhf(in_ + r * hn);
        float v = (1.0f - z) * n + z * (&hp.x)[u];
        ho[u] = v;
        hhv[u] = __float2half_rn(v);
    }
    *(float4*)(h + idx) = make_float4(ho[0], ho[1], ho[2], ho[3]);
    *(uint2*)(hh + idx) = *(uint2*)hhv;
}

// ---------------- GRU combine layer 1 (vectorized x4) ------------------------
__global__ void combine1(const float* __restrict__ gi,
                         const float* __restrict__ gh,
                         float* __restrict__ h,
                         __half* __restrict__ hh,
                         const float* __restrict__ bih,
                         const float* __restrict__ bhh)
{
    int v4 = blockIdx.x * blockDim.x + threadIdx.x;
    if (v4 >= Nq * Hq / 4) return;
    int idx = v4 * 4;
    int i = idx >> 9;
    int j = idx & (Hq - 1);

    const float* a = gi + (size_t)i * G3;
    const float* g = gh + (size_t)i * G3;

    float4 ar = *(const float4*)(a + 0 * Hq + j);
    float4 az = *(const float4*)(a + 1 * Hq + j);
    float4 an = *(const float4*)(a + 2 * Hq + j);
    float4 gr = *(const float4*)(g + 0 * Hq + j);
    float4 gz = *(const float4*)(g + 1 * Hq + j);
    float4 gn = *(const float4*)(g + 2 * Hq + j);
    float4 br_i = *(const float4*)(bih + 0 * Hq + j);
    float4 bz_i = *(const float4*)(bih + 1 * Hq + j);
    float4 bn_i = *(const float4*)(bih + 2 * Hq + j);
    float4 br_h = *(const float4*)(bhh + 0 * Hq + j);
    float4 bz_h = *(const float4*)(bhh + 1 * Hq + j);
    float4 bn_h = *(const float4*)(bhh + 2 * Hq + j);
    float4 hp = *(const float4*)(h + idx);

    float ho[4]; __half hhv[4];
#pragma unroll
    for (int u = 0; u < 4; u++) {
        float ir  = (&ar.x)[u] + (&br_i.x)[u];
        float iz  = (&az.x)[u] + (&bz_i.x)[u];
        float in_ = (&an.x)[u] + (&bn_i.x)[u];
        float hr  = (&gr.x)[u] + (&br_h.x)[u];
        float hz  = (&gz.x)[u] + (&bz_h.x)[u];
        float hn  = (&gn.x)[u] + (&bn_h.x)[u];

        float r = 1.0f / (1.0f + expf(-(ir + hr)));
        float z = 1.0f / (1.0f + expf(-(iz + hz)));
        float n = tanhf(in_ + r * hn);
        float v = (1.0f - z) * n + z * (&hp.x)[u];
        ho[u] = v;
        hhv[u] = __float2half_rn(v);
    }
    *(float4*)(h + idx) = make_float4(ho[0], ho[1], ho[2], ho[3]);
    *(uint2*)(hh + idx) = *(uint2*)hhv;
}

// ---------------- prediction: pred = Mh @ W2^T + b2 --------------------------
__global__ void pred_kernel(const float* __restrict__ Mh,
                            const float* __restrict__ W2,
                            const float* __restrict__ b2,
                            float* __restrict__ out, int t)
{
    int gwarp = (blockIdx.x * blockDim.x + threadIdx.x) >> 5;
    int lane  = threadIdx.x & 31;
    if (gwarp >= Nq) return;

    const float* mrow = Mh + (size_t)gwarp * MH;
    float s0 = 0.0f, s1 = 0.0f;
#pragma unroll
    for (int u = 0; u < 8; u++) {
        float m = mrow[lane + 32 * u];
        s0 = fmaf(m, W2[      lane + 32 * u], s0);
        s1 = fmaf(m, W2[MH +  lane + 32 * u], s1);
    }
#pragma unroll
    for (int off = 16; off; off >>= 1) {
        s0 += __shfl_xor_sync(0xFFFFFFFFu, s0, off);
        s1 += __shfl_xor_sync(0xFFFFFFFFu, s1, off);
    }
    if (lane == 0) {
        s0 += b2[0];
        s1 += b2[1];
        g_x[gwarp * 2 + 0] = s0;
        g_x[gwarp * 2 + 1] = s1;
        int b = gwarp >> 8;
        int a = gwarp & (Aq - 1);
        float* o = out + (((size_t)b * Tq + t) * Aq + a) * Oq;
        o[0] = s0;
        o[1] = s1;
    }
}

// ---------------- launch -----------------------------------------------------
extern "C" void kernel_launch(void* const* d_in, const int* in_sizes, int n_in,
                              void* d_out, int out_size)
{
    const float* social  = (const float*)d_in[0];
    const float* lastpos = (const float*)d_in[1];
    const float* Wih0    = (const float*)d_in[2];
    const float* Whh0    = (const float*)d_in[3];
    const float* bih0    = (const float*)d_in[4];
    const float* bhh0    = (const float*)d_in[5];
    const float* Wih1    = (const float*)d_in[6];
    const float* Whh1    = (const float*)d_in[7];
    const float* bih1    = (const float*)d_in[8];
    const float* bhh1    = (const float*)d_in[9];
    const float* W1      = (const float*)d_in[10];
    const float* b1      = (const float*)d_in[11];
    const float* W2      = (const float*)d_in[12];
    const float* b2      = (const float*)d_in[13];
    float* out = (float*)d_out;

    float *h0, *h1, *gate0, *gate1, *mbuf;
    __half *h0h, *h1h;
    __half *whh0hi, *whh0lo, *wih1hi, *wih1lo, *whh1hi, *whh1lo, *w1hi, *w1lo;
    cudaGetSymbolAddress((void**)&h0,    g_h0);
    cudaGetSymbolAddress((void**)&h1,    g_h1);
    cudaGetSymbolAddress((void**)&gate0, g_gate0);
    cudaGetSymbolAddress((void**)&gate1, g_gate1);
    cudaGetSymbolAddress((void**)&mbuf,  g_m);
    cudaGetSymbolAddress((void**)&h0h,   g_h0h);
    cudaGetSymbolAddress((void**)&h1h,   g_h1h);
    cudaGetSymbolAddress((void**)&whh0hi, g_Whh0hi);
    cudaGetSymbolAddress((void**)&whh0lo, g_Whh0lo);
    cudaGetSymbolAddress((void**)&wih1hi, g_Wih1hi);
    cudaGetSymbolAddress((void**)&wih1lo, g_Wih1lo);
    cudaGetSymbolAddress((void**)&whh1hi, g_Whh1hi);
    cudaGetSymbolAddress((void**)&whh1lo, g_Whh1lo);
    cudaGetSymbolAddress((void**)&w1hi,  g_W1hi);
    cudaGetSymbolAddress((void**)&w1lo,  g_W1lo);

    cudaFuncSetAttribute(gemm_mma, cudaFuncAttributeMaxDynamicSharedMemorySize, GEMM_SMEM);

    // split weights (fused, idempotent, every call)
    split_all<<<(SPLIT_TOTAL + 255) / 256, 256>>>(Whh0, Wih1, Whh1, W1);

    init_kernel<<<(Nq * Hq + 255) / 256, 256>>>(social, lastpos);

    dim3 gridGateDual(G3 / BN, Nq / BM, 2);  // 12 x 128 x 2
    dim3 gridGate(G3 / BN, Nq / BM, 1);      // 12 x 128
    dim3 gridMlp(MH / BN, Nq / BM, 1);       // 2  x 128
    int combBlocks = (Nq * Hq / 4 + 255) / 256;

    for (int t = 0; t < Tq; t++) {
        // merged: Gh0 = h0 @ Whh0^T  and  Gh1 = h1 @ Whh1^T  (independent)
        GemmSegs s0; s0.a[0] = h0h; s0.a[1] = h0h;
                     s0.w[0] = whh0hi; s0.w[1] = whh0lo;
        GemmSegs s2; s2.a[0] = h1h; s2.a[1] = h1h;
                     s2.w[0] = whh1hi; s2.w[1] = whh1lo;
        gemm_mma<<<gridGateDual, 256, GEMM_SMEM>>>(s0, s2, gate0, gate1, G3, nullptr, 0);
        combine0<<<combBlocks, 256>>>(gate0, h0, h0h, Wih0, bih0, bhh0);

        // Gi1 = h0n @ Wih1^T
        GemmSegs s1; s1.a[0] = h0h; s1.a[1] = h0h;
                     s1.w[0] = wih1hi; s1.w[1] = wih1lo;
        gemm_mma<<<gridGate, 256, GEMM_SMEM>>>(s1, s1, gate0, gate0, G3, nullptr, 0);
        combine1<<<combBlocks, 256>>>(gate0, gate1, h1, h1h, bih1, bhh1);

        // MLP hidden: m = relu(h1 @ W1^T + b1)
        GemmSegs s3; s3.a[0] = h1h; s3.a[1] = h1h;
                     s3.w[0] = w1hi; s3.w[1] = w1lo;
        gemm_mma<<<gridMlp, 256, GEMM_SMEM>>>(s3, s3, mbuf, mbuf, MH, b1, 1);
        pred_kernel<<<Nq * 32 / 256, 256>>>(mbuf, W2, b2, out, t);
    }
}